// round 1
// baseline (speedup 1.0000x reference)
#include <cuda_runtime.h>
#include <math.h>

// ---------------------------------------------------------------------------
// RG-LRU forward, T=8192, D_MODEL=768, D_RNN=1024, KW=4.
// Pipeline:
//   gemm1:  h = x @ w1^T + b1          -> gelu(h[:, :1024]) to g_ab, h[:,1024:] to g_bb
//   repack: conv_w [o][i][k] -> g_wc [o][k*1024+i]
//   gemmC:  bc = gatherShift(g_bb) @ g_wc^T     (causal conv as GEMM)
//   gemm3:  g = sigmoid(bc @ w_rg^T + b_rg)
//   atgx :  a_t = exp(-8*softplus(Lam)*rec), gx = sqrt(1-a^2)*inp*bc
//   scan :  3-phase chunked linear recurrence, fused z = a_branch * y
//   gemm4:  out = z @ w_out^T + b_out
// ---------------------------------------------------------------------------

#define T_LEN 8192
#define DM    768
#define DR    1024
#define KWW   4
#define NCH   64
#define CLEN  128   // NCH*CLEN == T_LEN

// scratch (static __device__ arrays; allocation-free per harness rules)
__device__ float g_ab[T_LEN * DR];       // gelu(a branch)
__device__ float g_bb[T_LEN * DR];       // raw b branch
__device__ float g_bc[T_LEN * DR];       // conv output
__device__ float g_gate[T_LEN * 2 * DR]; // sigmoid gates
__device__ float g_at[T_LEN * DR];
__device__ float g_gx[T_LEN * DR];
__device__ float g_z[T_LEN * DR];        // a_branch * y
__device__ float g_wc[DR * DR * KWW];    // repacked conv weights
__device__ float g_lam[DR];              // -8*softplus(Lambda)
__device__ float g_P[NCH * DR];
__device__ float g_L[NCH * DR];
__device__ float g_carry[NCH * DR];
__device__ float g_zero[4096];           // never written -> stays 0

// ---------------------------------------------------------------------------
// Generic SGEMM: C[M,N] = A[M,K] @ B[N,K]^T + bias
//   AMODE 0: A is plain row-major [M,K]
//   AMODE 1: A is g_bb-style gather: A[t, k*1024+i] = Abase[(t+k-3)*1024+i] (0 if t+k-3<0)
//   EPI   0: C[m*N+n] = v
//   EPI   1: n<1024 -> C[m*1024+n] = gelu(v); else C2[m*1024+n-1024] = v
//   EPI   2: C[m*N+n] = sigmoid(v)
// Tiles: 128x128x16, 256 threads, 8x8 per-thread microtile.
// Requires: M%128==0, N%128==0, K%16==0 (all shapes here satisfy this).
// ---------------------------------------------------------------------------
#define BM 128
#define BN 128
#define BK 16
#define TM 8
#define TN 8

__device__ __forceinline__ float gelu_f(float x) {
    // tanh approximation (jax.nn.gelu default, approximate=True)
    float x3 = x * x * x;
    float u  = 0.7978845608028654f * (x + 0.044715f * x3);
    return 0.5f * x * (1.0f + tanhf(u));
}

template <int AMODE, int EPI>
__global__ __launch_bounds__(256) void sgemm_kernel(
    const float* __restrict__ A, const float* __restrict__ B,
    const float* __restrict__ bias, float* __restrict__ C,
    float* __restrict__ C2, int M, int N, int K)
{
    __shared__ float As[BK][BM];
    __shared__ float Bs[BK][BN];

    const int tx = threadIdx.x;
    const int bm = blockIdx.y * BM;
    const int bn = blockIdx.x * BN;
    const int tr = tx >> 4;       // 0..15
    const int tc = tx & 15;       // 0..15

    const int lr = tx >> 2;       // 0..63  (load row within tile, +64 second half)
    const int lk = (tx & 3) * 4;  // 0,4,8,12

    float acc[TM][TN];
#pragma unroll
    for (int i = 0; i < TM; i++)
#pragma unroll
        for (int j = 0; j < TN; j++) acc[i][j] = 0.0f;

    for (int k0 = 0; k0 < K; k0 += BK) {
        // ---- load A tile (transposed into As[k][m]) ----
#pragma unroll
        for (int rr = 0; rr < 2; rr++) {
            int row = lr + rr * 64;
            int gm  = bm + row;
            float4 v;
            if (AMODE == 0) {
                v = *reinterpret_cast<const float4*>(&A[(size_t)gm * K + k0 + lk]);
            } else {
                int j    = k0 + lk;      // 0..4095
                int kk   = j >> 10;      // conv tap 0..3
                int i    = j & 1023;     // channel
                int srct = gm + kk - 3;  // causal shift
                if (srct >= 0)
                    v = *reinterpret_cast<const float4*>(&A[(size_t)srct * 1024 + i]);
                else
                    v = make_float4(0.f, 0.f, 0.f, 0.f);
            }
            As[lk + 0][row] = v.x;
            As[lk + 1][row] = v.y;
            As[lk + 2][row] = v.z;
            As[lk + 3][row] = v.w;
        }
        // ---- load B tile ----
#pragma unroll
        for (int rr = 0; rr < 2; rr++) {
            int row = lr + rr * 64;
            int gn  = bn + row;
            float4 v = *reinterpret_cast<const float4*>(&B[(size_t)gn * K + k0 + lk]);
            Bs[lk + 0][row] = v.x;
            Bs[lk + 1][row] = v.y;
            Bs[lk + 2][row] = v.z;
            Bs[lk + 3][row] = v.w;
        }
        __syncthreads();

#pragma unroll
        for (int kk = 0; kk < BK; kk++) {
            float af[TM], bf[TN];
            *reinterpret_cast<float4*>(&af[0]) = *reinterpret_cast<const float4*>(&As[kk][tr * TM]);
            *reinterpret_cast<float4*>(&af[4]) = *reinterpret_cast<const float4*>(&As[kk][tr * TM + 4]);
            *reinterpret_cast<float4*>(&bf[0]) = *reinterpret_cast<const float4*>(&Bs[kk][tc * TN]);
            *reinterpret_cast<float4*>(&bf[4]) = *reinterpret_cast<const float4*>(&Bs[kk][tc * TN + 4]);
#pragma unroll
            for (int i = 0; i < TM; i++)
#pragma unroll
                for (int j = 0; j < TN; j++)
                    acc[i][j] = fmaf(af[i], bf[j], acc[i][j]);
        }
        __syncthreads();
    }

    // ---- epilogue ----
#pragma unroll
    for (int i = 0; i < TM; i++) {
        int m = bm + tr * TM + i;
#pragma unroll
        for (int j = 0; j < TN; j++) {
            int n   = bn + tc * TN + j;
            float v = acc[i][j] + bias[n];
            if (EPI == 0) {
                C[(size_t)m * N + n] = v;
            } else if (EPI == 1) {
                if (n < DR) C[(size_t)m * DR + n] = gelu_f(v);
                else        C2[(size_t)m * DR + (n - DR)] = v;
            } else {
                C[(size_t)m * N + n] = 1.0f / (1.0f + expf(-v));
            }
        }
    }
}

// ---------------------------------------------------------------------------
// conv_w repack: src [o][i][k] (o*4096 + i*4 + k)  ->  g_wc [o][k*1024 + i]
// ---------------------------------------------------------------------------
__global__ void repack_conv_kernel(const float* __restrict__ w) {
    int idx = blockIdx.x * blockDim.x + threadIdx.x;
    if (idx >= DR * DR * KWW) return;
    int o   = idx >> 12;
    int rem = idx & 4095;
    int i   = rem >> 2;
    int k   = rem & 3;
    g_wc[(size_t)o * 4096 + k * 1024 + i] = w[idx];
}

// g_lam[c] = -8 * softplus(Lambda[c])
__global__ void lam_kernel(const float* __restrict__ Lambda) {
    int c = blockIdx.x * blockDim.x + threadIdx.x;
    if (c < DR) g_lam[c] = -8.0f * log1pf(expf(Lambda[c]));
}

// a_t, gated_x from sigmoid gates + bc
__global__ void atgx_kernel() {
    int idx = blockIdx.x * blockDim.x + threadIdx.x;
    if (idx >= T_LEN * DR) return;
    int c = idx & (DR - 1);
    int t = idx >> 10;
    float inp = g_gate[(size_t)t * (2 * DR) + c];
    float rec = g_gate[(size_t)t * (2 * DR) + DR + c];
    float a   = expf(g_lam[c] * rec);
    float bcv = g_bc[idx];
    g_at[idx] = a;
    g_gx[idx] = sqrtf(fmaxf(1.0f - a * a, 0.0f)) * inp * bcv;
}

// ---- 3-phase chunked linear scan: h_t = a_t * h_{t-1} + gx_t ----
__global__ void scan_phaseA_kernel() {
    int g = blockIdx.x * blockDim.x + threadIdx.x; // NCH*DR = 65536
    if (g >= NCH * DR) return;
    int c  = g & (DR - 1);
    int ch = g >> 10;
    size_t base = (size_t)ch * CLEN * DR + c;
    float P = 1.0f, L = 0.0f;
    for (int t = 0; t < CLEN; t++) {
        float a = g_at[base + (size_t)t * DR];
        float x = g_gx[base + (size_t)t * DR];
        L = fmaf(a, L, x);
        P *= a;
    }
    g_P[ch * DR + c] = P;
    g_L[ch * DR + c] = L;
}

__global__ void scan_phaseB_kernel() {
    int c = blockIdx.x * blockDim.x + threadIdx.x;
    if (c >= DR) return;
    float carry = 0.0f;
    for (int ch = 0; ch < NCH; ch++) {
        g_carry[ch * DR + c] = carry;
        carry = fmaf(g_P[ch * DR + c], carry, g_L[ch * DR + c]);
    }
}

__global__ void scan_phaseC_kernel() { // rescan with carry, fuse z = a_branch * y
    int g = blockIdx.x * blockDim.x + threadIdx.x;
    if (g >= NCH * DR) return;
    int c  = g & (DR - 1);
    int ch = g >> 10;
    size_t base = (size_t)ch * CLEN * DR + c;
    float h = g_carry[ch * DR + c];
    for (int t = 0; t < CLEN; t++) {
        size_t o = base + (size_t)t * DR;
        h = fmaf(g_at[o], h, g_gx[o]);
        g_z[o] = g_ab[o] * h;
    }
}

// ---------------------------------------------------------------------------
extern "C" void kernel_launch(void* const* d_in, const int* in_sizes, int n_in,
                              void* d_out, int out_size)
{
    const float* x      = (const float*)d_in[0];
    const float* w1     = (const float*)d_in[1];
    const float* b1     = (const float*)d_in[2];
    const float* conv_w = (const float*)d_in[3];
    const float* w_rg   = (const float*)d_in[4];
    const float* b_rg   = (const float*)d_in[5];
    const float* w_out  = (const float*)d_in[6];
    const float* b_out  = (const float*)d_in[7];
    const float* Lambda = (const float*)d_in[8];
    float* out = (float*)d_out;

    // symbol addresses for GEMM pointer args (host API calls are fine during capture)
    float *p_ab, *p_bb, *p_bc, *p_gate, *p_z, *p_wc, *p_zero;
    cudaGetSymbolAddress((void**)&p_ab,   g_ab);
    cudaGetSymbolAddress((void**)&p_bb,   g_bb);
    cudaGetSymbolAddress((void**)&p_bc,   g_bc);
    cudaGetSymbolAddress((void**)&p_gate, g_gate);
    cudaGetSymbolAddress((void**)&p_z,    g_z);
    cudaGetSymbolAddress((void**)&p_wc,   g_wc);
    cudaGetSymbolAddress((void**)&p_zero, g_zero);

    // small prep kernels
    lam_kernel<<<(DR + 255) / 256, 256>>>(Lambda);
    repack_conv_kernel<<<(DR * DR * KWW + 255) / 256, 256>>>(conv_w);

    // gemm1: h = x @ w1^T + b1 ; epilogue splits into gelu->g_ab, raw->g_bb
    {
        dim3 grid((2 * DR) / BN, T_LEN / BM);
        sgemm_kernel<0, 1><<<grid, 256>>>(x, w1, b1, p_ab, p_bb, T_LEN, 2 * DR, DM);
    }
    // conv as GEMM: bc = gather(g_bb) @ g_wc^T (zero bias)
    {
        dim3 grid(DR / BN, T_LEN / BM);
        sgemm_kernel<1, 0><<<grid, 256>>>(p_bb, p_wc, p_zero, p_bc, nullptr, T_LEN, DR, DR * KWW);
    }
    // gemm3: gates = sigmoid(bc @ w_rg^T + b_rg)
    {
        dim3 grid((2 * DR) / BN, T_LEN / BM);
        sgemm_kernel<0, 2><<<grid, 256>>>(p_bc, w_rg, b_rg, p_gate, nullptr, T_LEN, 2 * DR, DR);
    }
    // a_t / gated_x
    atgx_kernel<<<(T_LEN * DR + 255) / 256, 256>>>();

    // chunked scan
    scan_phaseA_kernel<<<(NCH * DR) / 256, 256>>>();
    scan_phaseB_kernel<<<(DR + 255) / 256, 256>>>();
    scan_phaseC_kernel<<<(NCH * DR) / 256, 256>>>();

    // gemm4: out = z @ w_out^T + b_out
    {
        dim3 grid(DM / BN, T_LEN / BM);
        sgemm_kernel<0, 0><<<grid, 256>>>(p_z, w_out, b_out, out, nullptr, T_LEN, DM, DR);
    }
}

// round 2
// speedup vs baseline: 2.0082x; 2.0082x over previous
#include <cuda_runtime.h>
#include <math.h>
#include <stdint.h>

// ---------------------------------------------------------------------------
// RG-LRU forward, T=8192, D_MODEL=768, D_RNN=1024, KW=4.
// All 4 GEMMs now run on tensor cores via mma.sync.m16n8k8 TF32 (fp32 accum).
// ---------------------------------------------------------------------------

#define T_LEN 8192
#define DM    768
#define DR    1024
#define KWW   4
#define NCH   64
#define CLEN  128

// scratch
__device__ float g_ab[T_LEN * DR];
__device__ float g_bb[T_LEN * DR];
__device__ float g_bc[T_LEN * DR];
__device__ float g_gate[T_LEN * 2 * DR];
__device__ float g_at[T_LEN * DR];
__device__ float g_gx[T_LEN * DR];
__device__ float g_z[T_LEN * DR];
__device__ float g_wc[DR * DR * KWW];
__device__ float g_lam[DR];
__device__ float g_P[NCH * DR];
__device__ float g_L[NCH * DR];
__device__ float g_carry[NCH * DR];
__device__ float g_zero[4096];

#define BM 128
#define BN 128
#define BKF 16          // K per smem tile
#define ROWPAD 20       // floats per smem row (16 + 4 pad) -> conflict-free frags

__device__ __forceinline__ float gelu_f(float x) {
    float x3 = x * x * x;
    float u  = 0.7978845608028654f * (x + 0.044715f * x3);
    return 0.5f * x * (1.0f + tanhf(u));
}

__device__ __forceinline__ uint32_t f2tf32(float f) {
    uint32_t u;
    asm("cvt.rna.tf32.f32 %0, %1;" : "=r"(u) : "f"(f));
    return u;
}

__device__ __forceinline__ void mma_tf32(float d[4], const uint32_t a[4],
                                         const uint32_t b[2], const float c[4]) {
    asm volatile(
        "mma.sync.aligned.m16n8k8.row.col.f32.tf32.tf32.f32 "
        "{%0,%1,%2,%3}, {%4,%5,%6,%7}, {%8,%9}, {%10,%11,%12,%13};\n"
        : "=f"(d[0]), "=f"(d[1]), "=f"(d[2]), "=f"(d[3])
        : "r"(a[0]), "r"(a[1]), "r"(a[2]), "r"(a[3]),
          "r"(b[0]), "r"(b[1]),
          "f"(c[0]), "f"(c[1]), "f"(c[2]), "f"(c[3]));
}

// ---------------------------------------------------------------------------
// TF32 tensor-core GEMM: C[M,N] = A[M,K] @ B[N,K]^T + bias
//   AMODE 0: plain A      AMODE 1: causal-conv gather A (K = 4*1024 virtual)
//   EPI 0: raw   EPI 1: gelu/split   EPI 2: sigmoid
// ---------------------------------------------------------------------------
template <int AMODE, int EPI>
__global__ __launch_bounds__(256, 2) void tgemm_kernel(
    const float* __restrict__ A, const float* __restrict__ B,
    const float* __restrict__ bias, float* __restrict__ C,
    float* __restrict__ C2, int M, int N, int K)
{
    __shared__ float As[2][BM][ROWPAD];
    __shared__ float Bs[2][BN][ROWPAD];

    const int tx   = threadIdx.x;
    const int bm   = blockIdx.y * BM;
    const int bn   = blockIdx.x * BN;
    const int wid  = tx >> 5;
    const int lane = tx & 31;
    const int wm   = (wid >> 1) * 32;   // warp M offset (4 warps along M)
    const int wn   = (wid & 1) * 64;    // warp N offset (2 warps along N)
    const int qr   = lane >> 2;         // 0..7
    const int qc   = lane & 3;          // 0..3

    const int lrow = tx >> 2;           // 0..63 (+64 for second chunk)
    const int lkq  = (tx & 3) * 4;      // 0,4,8,12

    float acc[2][8][4];
#pragma unroll
    for (int mi = 0; mi < 2; mi++)
#pragma unroll
        for (int ni = 0; ni < 8; ni++)
#pragma unroll
            for (int r = 0; r < 4; r++) acc[mi][ni][r] = 0.0f;

    const int ntiles = K / BKF;
    float4 ra[2], rb[2];

    // ---- global load of one K-tile into regs ----
    auto load_regs = [&](int t) {
        int k0 = t * BKF;
#pragma unroll
        for (int p = 0; p < 2; p++) {
            int row = lrow + p * 64;
            if (AMODE == 0) {
                ra[p] = *reinterpret_cast<const float4*>(
                    &A[(size_t)(bm + row) * K + k0 + lkq]);
            } else {
                int j    = k0 + lkq;
                int kk   = j >> 10;
                int i    = j & 1023;
                int srct = bm + row + kk - 3;
                ra[p] = (srct >= 0)
                    ? *reinterpret_cast<const float4*>(&A[(size_t)srct * 1024 + i])
                    : make_float4(0.f, 0.f, 0.f, 0.f);
            }
            rb[p] = *reinterpret_cast<const float4*>(
                &B[(size_t)(bn + row) * K + k0 + lkq]);
        }
    };

    auto sts = [&](int buf) {
#pragma unroll
        for (int p = 0; p < 2; p++) {
            int row = lrow + p * 64;
            float4 av = make_float4(__uint_as_float(f2tf32(ra[p].x)),
                                    __uint_as_float(f2tf32(ra[p].y)),
                                    __uint_as_float(f2tf32(ra[p].z)),
                                    __uint_as_float(f2tf32(ra[p].w)));
            float4 bv = make_float4(__uint_as_float(f2tf32(rb[p].x)),
                                    __uint_as_float(f2tf32(rb[p].y)),
                                    __uint_as_float(f2tf32(rb[p].z)),
                                    __uint_as_float(f2tf32(rb[p].w)));
            *reinterpret_cast<float4*>(&As[buf][row][lkq]) = av;
            *reinterpret_cast<float4*>(&Bs[buf][row][lkq]) = bv;
        }
    };

    auto compute = [&](int buf) {
#pragma unroll
        for (int kk = 0; kk < 2; kk++) {
            int kb = kk * 8;
            uint32_t af[2][4];
#pragma unroll
            for (int mi = 0; mi < 2; mi++) {
                int r0 = wm + mi * 16 + qr;
                af[mi][0] = __float_as_uint(As[buf][r0][kb + qc]);
                af[mi][1] = __float_as_uint(As[buf][r0 + 8][kb + qc]);
                af[mi][2] = __float_as_uint(As[buf][r0][kb + qc + 4]);
                af[mi][3] = __float_as_uint(As[buf][r0 + 8][kb + qc + 4]);
            }
            uint32_t bf[8][2];
#pragma unroll
            for (int ni = 0; ni < 8; ni++) {
                int nr = wn + ni * 8 + qr;
                bf[ni][0] = __float_as_uint(Bs[buf][nr][kb + qc]);
                bf[ni][1] = __float_as_uint(Bs[buf][nr][kb + qc + 4]);
            }
#pragma unroll
            for (int mi = 0; mi < 2; mi++)
#pragma unroll
                for (int ni = 0; ni < 8; ni++)
                    mma_tf32(acc[mi][ni], af[mi], bf[ni], acc[mi][ni]);
        }
    };

    // ---- pipelined mainloop ----
    load_regs(0);
    sts(0);
    __syncthreads();
    for (int t = 0; t < ntiles; t++) {
        if (t + 1 < ntiles) load_regs(t + 1);
        compute(t & 1);
        if (t + 1 < ntiles) {
            sts((t + 1) & 1);
        }
        __syncthreads();
    }

    // ---- epilogue ----
#pragma unroll
    for (int mi = 0; mi < 2; mi++) {
#pragma unroll
        for (int ni = 0; ni < 8; ni++) {
#pragma unroll
            for (int half = 0; half < 2; half++) {
                int m = bm + wm + mi * 16 + qr + half * 8;
                int n = bn + wn + ni * 8 + 2 * qc;
                float v0 = acc[mi][ni][half * 2 + 0] + bias[n];
                float v1 = acc[mi][ni][half * 2 + 1] + bias[n + 1];
                if (EPI == 0) {
                    C[(size_t)m * N + n]     = v0;
                    C[(size_t)m * N + n + 1] = v1;
                } else if (EPI == 1) {
                    if (n < DR) {
                        C[(size_t)m * DR + n]     = gelu_f(v0);
                        C[(size_t)m * DR + n + 1] = gelu_f(v1);
                    } else {
                        C2[(size_t)m * DR + (n - DR)]     = v0;
                        C2[(size_t)m * DR + (n - DR) + 1] = v1;
                    }
                } else {
                    C[(size_t)m * N + n]     = 1.0f / (1.0f + expf(-v0));
                    C[(size_t)m * N + n + 1] = 1.0f / (1.0f + expf(-v1));
                }
            }
        }
    }
}

// ---------------------------------------------------------------------------
__global__ void repack_conv_kernel(const float* __restrict__ w) {
    int idx = blockIdx.x * blockDim.x + threadIdx.x;
    if (idx >= DR * DR * KWW) return;
    int o   = idx >> 12;
    int rem = idx & 4095;
    int i   = rem >> 2;
    int k   = rem & 3;
    g_wc[(size_t)o * 4096 + k * 1024 + i] = w[idx];
}

__global__ void lam_kernel(const float* __restrict__ Lambda) {
    int c = blockIdx.x * blockDim.x + threadIdx.x;
    if (c < DR) g_lam[c] = -8.0f * log1pf(expf(Lambda[c]));
}

__global__ void atgx_kernel() {
    int idx = blockIdx.x * blockDim.x + threadIdx.x;
    if (idx >= T_LEN * DR) return;
    int c = idx & (DR - 1);
    int t = idx >> 10;
    float inp = g_gate[(size_t)t * (2 * DR) + c];
    float rec = g_gate[(size_t)t * (2 * DR) + DR + c];
    float a   = expf(g_lam[c] * rec);
    float bcv = g_bc[idx];
    g_at[idx] = a;
    g_gx[idx] = sqrtf(fmaxf(1.0f - a * a, 0.0f)) * inp * bcv;
}

__global__ void scan_phaseA_kernel() {
    int g = blockIdx.x * blockDim.x + threadIdx.x;
    if (g >= NCH * DR) return;
    int c  = g & (DR - 1);
    int ch = g >> 10;
    size_t base = (size_t)ch * CLEN * DR + c;
    float P = 1.0f, L = 0.0f;
    for (int t = 0; t < CLEN; t++) {
        float a = g_at[base + (size_t)t * DR];
        float x = g_gx[base + (size_t)t * DR];
        L = fmaf(a, L, x);
        P *= a;
    }
    g_P[ch * DR + c] = P;
    g_L[ch * DR + c] = L;
}

__global__ void scan_phaseB_kernel() {
    int c = blockIdx.x * blockDim.x + threadIdx.x;
    if (c >= DR) return;
    float carry = 0.0f;
    for (int ch = 0; ch < NCH; ch++) {
        g_carry[ch * DR + c] = carry;
        carry = fmaf(g_P[ch * DR + c], carry, g_L[ch * DR + c]);
    }
}

__global__ void scan_phaseC_kernel() {
    int g = blockIdx.x * blockDim.x + threadIdx.x;
    if (g >= NCH * DR) return;
    int c  = g & (DR - 1);
    int ch = g >> 10;
    size_t base = (size_t)ch * CLEN * DR + c;
    float h = g_carry[ch * DR + c];
    for (int t = 0; t < CLEN; t++) {
        size_t o = base + (size_t)t * DR;
        h = fmaf(g_at[o], h, g_gx[o]);
        g_z[o] = g_ab[o] * h;
    }
}

// ---------------------------------------------------------------------------
extern "C" void kernel_launch(void* const* d_in, const int* in_sizes, int n_in,
                              void* d_out, int out_size)
{
    const float* x      = (const float*)d_in[0];
    const float* w1     = (const float*)d_in[1];
    const float* b1     = (const float*)d_in[2];
    const float* conv_w = (const float*)d_in[3];
    const float* w_rg   = (const float*)d_in[4];
    const float* b_rg   = (const float*)d_in[5];
    const float* w_out  = (const float*)d_in[6];
    const float* b_out  = (const float*)d_in[7];
    const float* Lambda = (const float*)d_in[8];
    float* out = (float*)d_out;

    float *p_ab, *p_bb, *p_bc, *p_gate, *p_z, *p_wc, *p_zero;
    cudaGetSymbolAddress((void**)&p_ab,   g_ab);
    cudaGetSymbolAddress((void**)&p_bb,   g_bb);
    cudaGetSymbolAddress((void**)&p_bc,   g_bc);
    cudaGetSymbolAddress((void**)&p_gate, g_gate);
    cudaGetSymbolAddress((void**)&p_z,    g_z);
    cudaGetSymbolAddress((void**)&p_wc,   g_wc);
    cudaGetSymbolAddress((void**)&p_zero, g_zero);

    lam_kernel<<<(DR + 255) / 256, 256>>>(Lambda);
    repack_conv_kernel<<<(DR * DR * KWW + 255) / 256, 256>>>(conv_w);

    // gemm1: h = x @ w1^T + b1 ; split into gelu->g_ab, raw->g_bb
    {
        dim3 grid((2 * DR) / BN, T_LEN / BM);
        tgemm_kernel<0, 1><<<grid, 256>>>(x, w1, b1, p_ab, p_bb, T_LEN, 2 * DR, DM);
    }
    // conv as GEMM
    {
        dim3 grid(DR / BN, T_LEN / BM);
        tgemm_kernel<1, 0><<<grid, 256>>>(p_bb, p_wc, p_zero, p_bc, nullptr, T_LEN, DR, DR * KWW);
    }
    // gemm3: gates
    {
        dim3 grid((2 * DR) / BN, T_LEN / BM);
        tgemm_kernel<0, 2><<<grid, 256>>>(p_bc, w_rg, b_rg, p_gate, nullptr, T_LEN, 2 * DR, DR);
    }
    atgx_kernel<<<(T_LEN * DR + 255) / 256, 256>>>();
    scan_phaseA_kernel<<<(NCH * DR) / 256, 256>>>();
    scan_phaseB_kernel<<<(DR + 255) / 256, 256>>>();
    scan_phaseC_kernel<<<(NCH * DR) / 256, 256>>>();
    // gemm4: out
    {
        dim3 grid(DM / BN, T_LEN / BM);
        tgemm_kernel<0, 0><<<grid, 256>>>(p_z, w_out, b_out, out, nullptr, T_LEN, DM, DR);
    }
}

// round 4
// speedup vs baseline: 3.9364x; 1.9602x over previous
#include <cuda_runtime.h>
#include <math.h>
#include <stdint.h>

// ---------------------------------------------------------------------------
// RG-LRU forward, T=8192, D_MODEL=768, D_RNN=1024, KW=4.
// GEMMs: mma.sync.m16n8k8 TF32 + ldmatrix fragments + cp.async 3-stage ring.
// All GEMM operands pre-rounded to tf32 (cvt.rna) in gmem, once.
// ---------------------------------------------------------------------------

#define T_LEN 8192
#define DM    768
#define DR    1024
#define NCHK  64
#define CLEN  128

#define NSTAGE 3
#define BKF    32                 // K floats per stage
#define STAGE_BYTES (2 * 128 * BKF * 4)   // A tile 16KB + B tile 16KB

// scratch
__device__ float g_ab[T_LEN * DR];        // gelu(a branch), full fp32
__device__ float g_bb[T_LEN * DR];        // b branch, tf32-rounded (conv A input)
__device__ float g_bcr[T_LEN * DR];       // conv out, tf32-rounded (gemm3 A input)
__device__ float g_bc[T_LEN * DR];        // conv out, full fp32 (for gated_x)
__device__ float g_at[T_LEN * DR];
__device__ float g_gx[T_LEN * DR];
__device__ float g_z[T_LEN * DR];         // a_branch*y, tf32-rounded (gemm4 A input)
__device__ float g_wc[DR * DR * 4];       // conv weights repacked+rounded
__device__ float g_xr[T_LEN * DM];        // x rounded
__device__ float g_w1r[2 * DR * DM];
__device__ float g_wrgp[2 * DR * DR];     // w_rg row-permuted + rounded
__device__ float g_brgp[2 * DR];          // b_rg permuted
__device__ float g_woutr[DM * DR];
__device__ float g_lam[DR];
__device__ float g_P[NCHK * DR];
__device__ float g_L[NCHK * DR];
__device__ float g_carry[NCHK * DR];
__device__ float g_zero[4096];

// ---------------- helpers ----------------
__device__ __forceinline__ uint32_t smem_u32(const void* p) {
    uint32_t a;
    asm("{ .reg .u64 t; cvta.to.shared.u64 t, %1; cvt.u32.u64 %0, t; }" : "=r"(a) : "l"(p));
    return a;
}
__device__ __forceinline__ uint32_t f2tf32(float f) {
    uint32_t u; asm("cvt.rna.tf32.f32 %0, %1;" : "=r"(u) : "f"(f)); return u;
}
__device__ __forceinline__ float roundtf(float f) { return __uint_as_float(f2tf32(f)); }

__device__ __forceinline__ float gelu_f(float x) {
    float x3 = x * x * x;
    float u  = 0.7978845608028654f * (x + 0.044715f * x3);
    return 0.5f * x * (1.0f + tanhf(u));
}
__device__ __forceinline__ float sigm(float x) { return 1.0f / (1.0f + expf(-x)); }

#define SW128(o) ((o) ^ ((((uint32_t)(o)) >> 3) & 0x70u))

__device__ __forceinline__ void cp16(uint32_t dst, const void* src, bool pred) {
    int sz = pred ? 16 : 0;
    asm volatile("cp.async.cg.shared.global [%0], [%1], 16, %2;\n"
                 :: "r"(dst), "l"(src), "r"(sz) : "memory");
}
__device__ __forceinline__ void cp_commit() {
    asm volatile("cp.async.commit_group;" ::: "memory");
}
__device__ __forceinline__ void ldsm4(uint32_t r[4], uint32_t addr) {
    asm volatile("ldmatrix.sync.aligned.m8n8.x4.shared.b16 {%0,%1,%2,%3}, [%4];"
                 : "=r"(r[0]), "=r"(r[1]), "=r"(r[2]), "=r"(r[3]) : "r"(addr));
}
__device__ __forceinline__ void mma_tf32(float d[4], const uint32_t a[4],
                                         const uint32_t b[2], const float c[4]) {
    asm volatile(
        "mma.sync.aligned.m16n8k8.row.col.f32.tf32.tf32.f32 "
        "{%0,%1,%2,%3}, {%4,%5,%6,%7}, {%8,%9}, {%10,%11,%12,%13};\n"
        : "=f"(d[0]), "=f"(d[1]), "=f"(d[2]), "=f"(d[3])
        : "r"(a[0]), "r"(a[1]), "r"(a[2]), "r"(a[3]),
          "r"(b[0]), "r"(b[1]),
          "f"(c[0]), "f"(c[1]), "f"(c[2]), "f"(c[3]));
}

// ---------------------------------------------------------------------------
// TF32 tensor-core GEMM: C[M,N] = A[M,K] @ B[N,K]^T + bias, 128x128 CTA tile.
//   AMODE 0: plain A      AMODE 1: causal-conv gather A (K = 4*1024 virtual)
//   EPI 0: raw   EPI 1: gelu / tf32-split   EPI 3: rounded+full split
//   EPI 4: fused gates: sigmoid pair -> a_t / gated_x (uses Xbc, lam)
// ---------------------------------------------------------------------------
template <int AMODE, int EPI>
__global__ __launch_bounds__(256, 2) void tgemm(
    const float* __restrict__ A, const float* __restrict__ B,
    const float* __restrict__ bias, float* __restrict__ C,
    float* __restrict__ C2, const float* __restrict__ Xbc,
    const float* __restrict__ lam, int M, int N, int K)
{
    extern __shared__ char dynsm[];
    const uint32_t sb = (smem_u32(dynsm) + 1023u) & ~1023u;

    const int tid  = threadIdx.x;
    const int wid  = tid >> 5;
    const int lane = tid & 31;
    const int bm   = blockIdx.y * 128;
    const int bn   = blockIdx.x * 128;
    const int wm   = (wid >> 1) * 32;     // 4 warps along M
    const int wn   = (wid & 1) * 64;      // 2 warps along N
    const int qr   = lane >> 2;
    const int qc   = lane & 3;

    // ldmatrix per-lane source rows
    const int arow  = wm + (lane & 15);
    const int ahalf = (lane >> 4) & 1;            // 0/1 -> +16B (k 4..7)
    const int brow  = wn + (lane & 7) + ((lane >> 4) << 3);
    const int bhalf = (lane >> 3) & 1;

    float acc[2][8][4];
#pragma unroll
    for (int mi = 0; mi < 2; mi++)
#pragma unroll
        for (int ni = 0; ni < 8; ni++)
#pragma unroll
            for (int r = 0; r < 4; r++) acc[mi][ni][r] = 0.0f;

    const int nch = K / BKF;

    auto issue_chunk = [&](int c) {
        const int s = c % NSTAGE;
        const uint32_t abase = sb + s * STAGE_BYTES;
        const uint32_t bbase = abase + 128 * BKF * 4;
        const int k0 = c * BKF;
#pragma unroll
        for (int q = 0; q < 4; q++) {
            int id  = tid + q * 256;    // 0..1023
            int row = id >> 3;
            int c16 = id & 7;           // 16B chunk within 128B row
            const float* asrc;
            bool pred = true;
            if (AMODE == 0) {
                asrc = A + (size_t)(bm + row) * K + k0 + c16 * 4;
            } else {
                int j    = k0 + c16 * 4;
                int tap  = j >> 10;
                int i    = j & 1023;
                int srct = bm + row + tap - 3;
                pred = (srct >= 0);
                asrc = A + (pred ? ((size_t)srct * 1024 + i) : 0);
            }
            cp16(abase + SW128(row * 128 + c16 * 16), asrc, pred);
            const float* bsrc = B + (size_t)(bn + row) * K + k0 + c16 * 4;
            cp16(bbase + SW128(row * 128 + c16 * 16), bsrc, true);
        }
        cp_commit();
    };

    auto compute = [&](int s) {
        const uint32_t abase = sb + s * STAGE_BYTES;
        const uint32_t bbase = abase + 128 * BKF * 4;
#pragma unroll
        for (int kb = 0; kb < 4; kb++) {
            uint32_t af[2][4];
#pragma unroll
            for (int mi = 0; mi < 2; mi++)
                ldsm4(af[mi], abase + SW128((arow + mi * 16) * 128 + kb * 32 + ahalf * 16));
            uint32_t bf[4][4];
#pragma unroll
            for (int p = 0; p < 4; p++)
                ldsm4(bf[p], bbase + SW128((brow + p * 16) * 128 + kb * 32 + bhalf * 16));
#pragma unroll
            for (int mi = 0; mi < 2; mi++)
#pragma unroll
                for (int ni = 0; ni < 8; ni++)
                    mma_tf32(acc[mi][ni], af[mi], &bf[ni >> 1][(ni & 1) * 2], acc[mi][ni]);
        }
    };

    // ---------------- pipelined mainloop ----------------
    issue_chunk(0);
    issue_chunk(1);
    asm volatile("cp.async.wait_group %0;" :: "n"(NSTAGE - 2) : "memory");
    __syncthreads();

    for (int c = 0; c < nch; c++) {
        compute(c % NSTAGE);
        __syncthreads();
        if (c + 2 < nch) issue_chunk(c + 2);
        else             cp_commit();
        asm volatile("cp.async.wait_group %0;" :: "n"(NSTAGE - 2) : "memory");
        __syncthreads();
    }

    // ---------------- epilogue ----------------
#pragma unroll
    for (int mi = 0; mi < 2; mi++) {
#pragma unroll
        for (int ni = 0; ni < 8; ni++) {
#pragma unroll
            for (int half = 0; half < 2; half++) {
                int m = bm + wm + mi * 16 + qr + half * 8;
                int n = bn + wn + ni * 8 + 2 * qc;
                float v0 = acc[mi][ni][half * 2 + 0] + bias[n];
                float v1 = acc[mi][ni][half * 2 + 1] + bias[n + 1];
                if (EPI == 0) {
                    C[(size_t)m * N + n]     = v0;
                    C[(size_t)m * N + n + 1] = v1;
                } else if (EPI == 1) {
                    if (n < DR) {
                        C[(size_t)m * DR + n]     = gelu_f(v0);
                        C[(size_t)m * DR + n + 1] = gelu_f(v1);
                    } else {
                        C2[(size_t)m * DR + (n - DR)]     = roundtf(v0);
                        C2[(size_t)m * DR + (n - DR) + 1] = roundtf(v1);
                    }
                } else if (EPI == 3) {
                    C[(size_t)m * N + n]      = roundtf(v0);
                    C[(size_t)m * N + n + 1]  = roundtf(v1);
                    C2[(size_t)m * N + n]     = v0;
                    C2[(size_t)m * N + n + 1] = v1;
                } else {  // EPI == 4 : fused gate pair (inp, rec) for channel ch
                    int ch    = n >> 1;
                    float inp = sigm(v0);
                    float rec = sigm(v1);
                    float a   = expf(lam[ch] * rec);
                    float gx  = sqrtf(fmaxf(1.0f - a * a, 0.0f)) * inp *
                                Xbc[(size_t)m * DR + ch];
                    C[(size_t)m * DR + ch]  = a;   // g_at
                    C2[(size_t)m * DR + ch] = gx;  // g_gx
                }
            }
        }
    }
}

// ---------------------------------------------------------------------------
__global__ void round_copy_kernel(const float* __restrict__ src,
                                  float* __restrict__ dst, int n) {
    int i = blockIdx.x * blockDim.x + threadIdx.x;
    if (i < n) dst[i] = roundtf(src[i]);
}

// conv_w [o][i][k] -> g_wc [o][k*1024+i], rounded
__global__ void repack_conv_kernel(const float* __restrict__ w) {
    int idx = blockIdx.x * blockDim.x + threadIdx.x;
    if (idx >= DR * DR * 4) return;
    int o   = idx >> 12;
    int rem = idx & 4095;
    int i   = rem >> 2;
    int k   = rem & 3;
    g_wc[(size_t)o * 4096 + k * 1024 + i] = roundtf(w[idx]);
}

// w_rg row permute: dst row 2c = src row c (inp), dst 2c+1 = src 1024+c (rec)
__global__ void permute_wrg_kernel(const float* __restrict__ w,
                                   const float* __restrict__ b) {
    int idx = blockIdx.x * blockDim.x + threadIdx.x;
    if (idx >= 2 * DR * DR) return;
    int r = idx >> 10;        // dst row
    int k = idx & 1023;
    int srcr = (r & 1) ? (DR + (r >> 1)) : (r >> 1);
    g_wrgp[idx] = roundtf(w[(size_t)srcr * DR + k]);
    if (k == 0) g_brgp[r] = b[srcr];
}

__global__ void lam_kernel(const float* __restrict__ Lambda) {
    int c = blockIdx.x * blockDim.x + threadIdx.x;
    if (c < DR) g_lam[c] = -8.0f * log1pf(expf(Lambda[c]));
}

// ---- 3-phase chunked linear scan ----
__global__ void scan_phaseA_kernel() {
    int g = blockIdx.x * blockDim.x + threadIdx.x;
    if (g >= NCHK * DR) return;
    int c  = g & (DR - 1);
    int ch = g >> 10;
    size_t base = (size_t)ch * CLEN * DR + c;
    float P = 1.0f, L = 0.0f;
    for (int t = 0; t < CLEN; t++) {
        float a = g_at[base + (size_t)t * DR];
        float x = g_gx[base + (size_t)t * DR];
        L = fmaf(a, L, x);
        P *= a;
    }
    g_P[ch * DR + c] = P;
    g_L[ch * DR + c] = L;
}

__global__ void scan_phaseB_kernel() {
    int c = blockIdx.x * blockDim.x + threadIdx.x;
    if (c >= DR) return;
    float carry = 0.0f;
    for (int ch = 0; ch < NCHK; ch++) {
        g_carry[ch * DR + c] = carry;
        carry = fmaf(g_P[ch * DR + c], carry, g_L[ch * DR + c]);
    }
}

__global__ void scan_phaseC_kernel() {
    int g = blockIdx.x * blockDim.x + threadIdx.x;
    if (g >= NCHK * DR) return;
    int c  = g & (DR - 1);
    int ch = g >> 10;
    size_t base = (size_t)ch * CLEN * DR + c;
    float h = g_carry[ch * DR + c];
    for (int t = 0; t < CLEN; t++) {
        size_t o = base + (size_t)t * DR;
        h = fmaf(g_at[o], h, g_gx[o]);
        g_z[o] = roundtf(g_ab[o] * h);
    }
}

// ---------------------------------------------------------------------------
extern "C" void kernel_launch(void* const* d_in, const int* in_sizes, int n_in,
                              void* d_out, int out_size)
{
    const float* x      = (const float*)d_in[0];
    const float* w1     = (const float*)d_in[1];
    const float* b1     = (const float*)d_in[2];
    const float* conv_w = (const float*)d_in[3];
    const float* w_rg   = (const float*)d_in[4];
    const float* b_rg   = (const float*)d_in[5];
    const float* w_out  = (const float*)d_in[6];
    const float* b_out  = (const float*)d_in[7];
    const float* Lambda = (const float*)d_in[8];
    float* out = (float*)d_out;

    float *p_ab, *p_bb, *p_bcr, *p_bc, *p_at, *p_gx, *p_z, *p_wc, *p_zero;
    float *p_xr, *p_w1r, *p_wrgp, *p_brgp, *p_woutr, *p_lam;
    cudaGetSymbolAddress((void**)&p_ab,    g_ab);
    cudaGetSymbolAddress((void**)&p_bb,    g_bb);
    cudaGetSymbolAddress((void**)&p_bcr,   g_bcr);
    cudaGetSymbolAddress((void**)&p_bc,    g_bc);
    cudaGetSymbolAddress((void**)&p_at,    g_at);
    cudaGetSymbolAddress((void**)&p_gx,    g_gx);
    cudaGetSymbolAddress((void**)&p_z,     g_z);
    cudaGetSymbolAddress((void**)&p_wc,    g_wc);
    cudaGetSymbolAddress((void**)&p_zero,  g_zero);
    cudaGetSymbolAddress((void**)&p_xr,    g_xr);
    cudaGetSymbolAddress((void**)&p_w1r,   g_w1r);
    cudaGetSymbolAddress((void**)&p_wrgp,  g_wrgp);
    cudaGetSymbolAddress((void**)&p_brgp,  g_brgp);
    cudaGetSymbolAddress((void**)&p_woutr, g_woutr);
    cudaGetSymbolAddress((void**)&p_lam,   g_lam);

    const int smem_bytes = NSTAGE * STAGE_BYTES + 1024;  // 97 KB
    cudaFuncSetAttribute(tgemm<0, 1>, cudaFuncAttributeMaxDynamicSharedMemorySize, smem_bytes);
    cudaFuncSetAttribute(tgemm<1, 3>, cudaFuncAttributeMaxDynamicSharedMemorySize, smem_bytes);
    cudaFuncSetAttribute(tgemm<0, 4>, cudaFuncAttributeMaxDynamicSharedMemorySize, smem_bytes);
    cudaFuncSetAttribute(tgemm<0, 0>, cudaFuncAttributeMaxDynamicSharedMemorySize, smem_bytes);

    // prep: round operands, repack conv, permute w_rg
    lam_kernel<<<(DR + 255) / 256, 256>>>(Lambda);
    repack_conv_kernel<<<(DR * DR * 4 + 255) / 256, 256>>>(conv_w);
    permute_wrg_kernel<<<(2 * DR * DR + 255) / 256, 256>>>(w_rg, b_rg);
    round_copy_kernel<<<(T_LEN * DM + 255) / 256, 256>>>(x, p_xr, T_LEN * DM);
    round_copy_kernel<<<(2 * DR * DM + 255) / 256, 256>>>(w1, p_w1r, 2 * DR * DM);
    round_copy_kernel<<<(DM * DR + 255) / 256, 256>>>(w_out, p_woutr, DM * DR);

    // gemm1: h = x @ w1^T + b1 ; gelu -> g_ab, rounded raw -> g_bb
    {
        dim3 grid((2 * DR) / 128, T_LEN / 128);
        tgemm<0, 1><<<grid, 256, smem_bytes>>>(p_xr, p_w1r, b1, p_ab, p_bb,
                                               nullptr, nullptr, T_LEN, 2 * DR, DM);
    }
    // conv as GEMM -> g_bcr (rounded) + g_bc (full)
    {
        dim3 grid(DR / 128, T_LEN / 128);
        tgemm<1, 3><<<grid, 256, smem_bytes>>>(p_bb, p_wc, p_zero, p_bcr, p_bc,
                                               nullptr, nullptr, T_LEN, DR, DR * 4);
    }
    // gemm3 (permuted) + fused gates -> g_at, g_gx
    {
        dim3 grid((2 * DR) / 128, T_LEN / 128);
        tgemm<0, 4><<<grid, 256, smem_bytes>>>(p_bcr, p_wrgp, p_brgp, p_at, p_gx,
                                               p_bc, p_lam, T_LEN, 2 * DR, DR);
    }
    scan_phaseA_kernel<<<(NCHK * DR) / 256, 256>>>();
    scan_phaseB_kernel<<<(DR + 255) / 256, 256>>>();
    scan_phaseC_kernel<<<(NCHK * DR) / 256, 256>>>();
    // gemm4: out = z @ w_out^T + b_out
    {
        dim3 grid(DM / 128, T_LEN / 128);
        tgemm<0, 0><<<grid, 256, smem_bytes>>>(p_z, p_woutr, b_out, out, nullptr,
                                               nullptr, nullptr, T_LEN, DM, DR);
    }
}

// round 5
// speedup vs baseline: 4.1078x; 1.0435x over previous
#include <cuda_runtime.h>
#include <math.h>
#include <stdint.h>

// ---------------------------------------------------------------------------
// RG-LRU forward, T=8192, D_MODEL=768, D_RNN=1024, KW=4.
// GEMMs: mma.sync.m16n8k8 TF32 + ldmatrix + cp.async 3-stage, 1 sync/chunk.
// ---------------------------------------------------------------------------

#define T_LEN 8192
#define DM    768
#define DR    1024
#define NCHK  64
#define CLEN  128

#define NSTAGE 3
#define BKF    32
#define STAGE_BYTES (2 * 128 * BKF * 4)

// scratch
__device__ float g_ab[T_LEN * DR];
__device__ float g_bb[T_LEN * DR];
__device__ float g_bcr[T_LEN * DR];      // conv out, tf32-rounded
__device__ float g_at[T_LEN * DR];
__device__ float g_gx[T_LEN * DR];
__device__ float g_z[T_LEN * DR];
__device__ float g_wc[DR * DR * 4];
__device__ float g_xr[T_LEN * DM];
__device__ float g_w1r[2 * DR * DM];
__device__ float g_wrgp[2 * DR * DR];
__device__ float g_brgp[2 * DR];
__device__ float g_woutr[DM * DR];
__device__ float g_lam[DR];
__device__ float g_P[NCHK * DR];
__device__ float g_L[NCHK * DR];
__device__ float g_carry[NCHK * DR];
__device__ float g_zero[4096];

// ---------------- helpers ----------------
__device__ __forceinline__ uint32_t smem_u32(const void* p) {
    uint32_t a;
    asm("{ .reg .u64 t; cvta.to.shared.u64 t, %1; cvt.u32.u64 %0, t; }" : "=r"(a) : "l"(p));
    return a;
}
__device__ __forceinline__ uint32_t f2tf32(float f) {
    uint32_t u; asm("cvt.rna.tf32.f32 %0, %1;" : "=r"(u) : "f"(f)); return u;
}
__device__ __forceinline__ float roundtf(float f) { return __uint_as_float(f2tf32(f)); }

__device__ __forceinline__ float gelu_f(float x) {
    float x3 = x * x * x;
    float u  = 0.7978845608028654f * (x + 0.044715f * x3);
    return 0.5f * x * (1.0f + tanhf(u));
}
__device__ __forceinline__ float sigm(float x) { return 1.0f / (1.0f + expf(-x)); }

#define SW128(o) ((o) ^ ((((uint32_t)(o)) >> 3) & 0x70u))

__device__ __forceinline__ void cp16(uint32_t dst, const void* src, bool pred) {
    int sz = pred ? 16 : 0;
    asm volatile("cp.async.cg.shared.global [%0], [%1], 16, %2;\n"
                 :: "r"(dst), "l"(src), "r"(sz) : "memory");
}
__device__ __forceinline__ void cp_commit() {
    asm volatile("cp.async.commit_group;" ::: "memory");
}
__device__ __forceinline__ void ldsm4(uint32_t r[4], uint32_t addr) {
    asm volatile("ldmatrix.sync.aligned.m8n8.x4.shared.b16 {%0,%1,%2,%3}, [%4];"
                 : "=r"(r[0]), "=r"(r[1]), "=r"(r[2]), "=r"(r[3]) : "r"(addr));
}
__device__ __forceinline__ void mma_tf32(float d[4], const uint32_t a[4],
                                         const uint32_t b[2], const float c[4]) {
    asm volatile(
        "mma.sync.aligned.m16n8k8.row.col.f32.tf32.tf32.f32 "
        "{%0,%1,%2,%3}, {%4,%5,%6,%7}, {%8,%9}, {%10,%11,%12,%13};\n"
        : "=f"(d[0]), "=f"(d[1]), "=f"(d[2]), "=f"(d[3])
        : "r"(a[0]), "r"(a[1]), "r"(a[2]), "r"(a[3]),
          "r"(b[0]), "r"(b[1]),
          "f"(c[0]), "f"(c[1]), "f"(c[2]), "f"(c[3]));
}

// ---------------------------------------------------------------------------
// TF32 GEMM: C[M,N] = A[M,K] @ B[N,K]^T + bias, 128x128 CTA tile.
//   AMODE 0: plain A    AMODE 1: causal-conv gather (K = 4*1024 virtual)
//   EPI 0: raw   EPI 1: gelu / tf32-split   EPI 4: fused gates   EPI 5: rounded
// ---------------------------------------------------------------------------
template <int AMODE, int EPI>
__global__ __launch_bounds__(256, 2) void tgemm(
    const float* __restrict__ A, const float* __restrict__ B,
    const float* __restrict__ bias, float* __restrict__ C,
    float* __restrict__ C2, const float* __restrict__ Xbc,
    const float* __restrict__ lam, int M, int N, int K)
{
    extern __shared__ char dynsm[];
    const uint32_t sb = (smem_u32(dynsm) + 1023u) & ~1023u;

    const int tid  = threadIdx.x;
    const int wid  = tid >> 5;
    const int lane = tid & 31;
    const int bm   = blockIdx.y * 128;
    const int bn   = blockIdx.x * 128;
    const int wm   = (wid >> 1) * 32;
    const int wn   = (wid & 1) * 64;
    const int qr   = lane >> 2;
    const int qc   = lane & 3;

    const int arow  = wm + (lane & 15);
    const int ahalf = (lane >> 4) & 1;
    const int brow  = wn + (lane & 7) + ((lane >> 4) << 3);
    const int bhalf = (lane >> 3) & 1;

    float acc[2][8][4];
#pragma unroll
    for (int mi = 0; mi < 2; mi++)
#pragma unroll
        for (int ni = 0; ni < 8; ni++)
#pragma unroll
            for (int r = 0; r < 4; r++) acc[mi][ni][r] = 0.0f;

    const int nch = K / BKF;

    auto issue_chunk = [&](int c) {
        const int s = c % NSTAGE;
        const uint32_t abase = sb + s * STAGE_BYTES;
        const uint32_t bbase = abase + 128 * BKF * 4;
        const int k0 = c * BKF;
#pragma unroll
        for (int q = 0; q < 4; q++) {
            int id  = tid + q * 256;
            int row = id >> 3;
            int c16 = id & 7;
            const float* asrc;
            bool pred = true;
            if (AMODE == 0) {
                asrc = A + (size_t)(bm + row) * K + k0 + c16 * 4;
            } else {
                int j    = k0 + c16 * 4;
                int tap  = j >> 10;
                int i    = j & 1023;
                int srct = bm + row + tap - 3;
                pred = (srct >= 0);
                asrc = A + (pred ? ((size_t)srct * 1024 + i) : 0);
            }
            cp16(abase + SW128(row * 128 + c16 * 16), asrc, pred);
            const float* bsrc = B + (size_t)(bn + row) * K + k0 + c16 * 4;
            cp16(bbase + SW128(row * 128 + c16 * 16), bsrc, true);
        }
        cp_commit();
    };

    auto compute = [&](int s) {
        const uint32_t abase = sb + s * STAGE_BYTES;
        const uint32_t bbase = abase + 128 * BKF * 4;
#pragma unroll
        for (int kb = 0; kb < 4; kb++) {
            uint32_t af[2][4];
#pragma unroll
            for (int mi = 0; mi < 2; mi++)
                ldsm4(af[mi], abase + SW128((arow + mi * 16) * 128 + kb * 32 + ahalf * 16));
            uint32_t bf[4][4];
#pragma unroll
            for (int p = 0; p < 4; p++)
                ldsm4(bf[p], bbase + SW128((brow + p * 16) * 128 + kb * 32 + bhalf * 16));
#pragma unroll
            for (int mi = 0; mi < 2; mi++)
#pragma unroll
                for (int ni = 0; ni < 8; ni++)
                    mma_tf32(acc[mi][ni], af[mi], &bf[ni >> 1][(ni & 1) * 2], acc[mi][ni]);
        }
    };

    // ---------------- mainloop: 1 sync per chunk ----------------
    issue_chunk(0);
    issue_chunk(1);
    for (int c = 0; c < nch; c++) {
        asm volatile("cp.async.wait_group %0;" :: "n"(1) : "memory");
        __syncthreads();
        compute(c % NSTAGE);
        // writes stage (c-1)%3: its last reader (compute(c-1)) is behind the
        // barrier above, so no second barrier needed.
        if (c + 2 < nch) issue_chunk(c + 2);
        else             cp_commit();
    }

    // ---------------- epilogue ----------------
#pragma unroll
    for (int mi = 0; mi < 2; mi++) {
#pragma unroll
        for (int ni = 0; ni < 8; ni++) {
#pragma unroll
            for (int half = 0; half < 2; half++) {
                int m = bm + wm + mi * 16 + qr + half * 8;
                int n = bn + wn + ni * 8 + 2 * qc;
                float v0 = acc[mi][ni][half * 2 + 0] + bias[n];
                float v1 = acc[mi][ni][half * 2 + 1] + bias[n + 1];
                if (EPI == 0) {
                    C[(size_t)m * N + n]     = v0;
                    C[(size_t)m * N + n + 1] = v1;
                } else if (EPI == 1) {
                    if (n < DR) {
                        C[(size_t)m * DR + n]     = gelu_f(v0);
                        C[(size_t)m * DR + n + 1] = gelu_f(v1);
                    } else {
                        C2[(size_t)m * DR + (n - DR)]     = roundtf(v0);
                        C2[(size_t)m * DR + (n - DR) + 1] = roundtf(v1);
                    }
                } else if (EPI == 5) {
                    C[(size_t)m * N + n]     = roundtf(v0);
                    C[(size_t)m * N + n + 1] = roundtf(v1);
                } else {  // EPI == 4 : fused gate pair (inp, rec) for channel n>>1
                    int ch    = n >> 1;
                    float inp = sigm(v0);
                    float rec = sigm(v1);
                    float a   = expf(lam[ch] * rec);
                    float gx  = sqrtf(fmaxf(1.0f - a * a, 0.0f)) * inp *
                                Xbc[(size_t)m * DR + ch];
                    C[(size_t)m * DR + ch]  = a;
                    C2[(size_t)m * DR + ch] = gx;
                }
            }
        }
    }
}

// ---------------------------------------------------------------------------
// prep 1: w_rg row-permute (+ b_rg permute + lam), float4 over k
__global__ void prep_wrg_kernel(const float* __restrict__ w,
                                const float* __restrict__ b,
                                const float* __restrict__ Lambda) {
    int gid = blockIdx.x * blockDim.x + threadIdx.x;   // 2*DR*DR/4 = 524288
    if (gid < 2 * DR) g_brgp[gid] = b[(gid & 1) ? (DR + (gid >> 1)) : (gid >> 1)];
    if (gid < DR)     g_lam[gid]  = -8.0f * log1pf(expf(Lambda[gid]));
    if (gid >= 2 * DR * DR / 4) return;
    int r  = gid >> 8;            // dst row (1024 float4 per row / 4 = 256)
    int k4 = gid & 255;
    int srcr = (r & 1) ? (DR + (r >> 1)) : (r >> 1);
    float4 v = *reinterpret_cast<const float4*>(&w[(size_t)srcr * DR + k4 * 4]);
    v.x = roundtf(v.x); v.y = roundtf(v.y); v.z = roundtf(v.z); v.w = roundtf(v.w);
    *reinterpret_cast<float4*>(&g_wrgp[(size_t)r * DR + k4 * 4]) = v;
}

// prep 2: conv_w [o][i][k] -> g_wc [o][k*1024+i]; one float4 read = 4 taps of (o,i)
__global__ void repack_conv_kernel(const float* __restrict__ w) {
    int gid = blockIdx.x * blockDim.x + threadIdx.x;   // DR*DR = 1048576
    if (gid >= DR * DR) return;
    int o = gid >> 10;
    int i = gid & 1023;
    float4 v = *reinterpret_cast<const float4*>(&w[(size_t)gid * 4]);
    size_t base = (size_t)o * 4096 + i;
    g_wc[base]        = roundtf(v.x);
    g_wc[base + 1024] = roundtf(v.y);
    g_wc[base + 2048] = roundtf(v.z);
    g_wc[base + 3072] = roundtf(v.w);
}

// prep 3: round x (float4)
__global__ void round_x_kernel(const float* __restrict__ src, float* __restrict__ dst) {
    int gid = blockIdx.x * blockDim.x + threadIdx.x;   // T_LEN*DM/4
    if (gid >= T_LEN * DM / 4) return;
    float4 v = reinterpret_cast<const float4*>(src)[gid];
    v.x = roundtf(v.x); v.y = roundtf(v.y); v.z = roundtf(v.z); v.w = roundtf(v.w);
    reinterpret_cast<float4*>(dst)[gid] = v;
}

// prep 4: round w1 + w_out in one kernel (float4)
__global__ void round_w_kernel(const float* __restrict__ w1, float* __restrict__ d1,
                               const float* __restrict__ w2, float* __restrict__ d2,
                               int n1_4, int n2_4) {
    int gid = blockIdx.x * blockDim.x + threadIdx.x;
    const float4* s; float4* d; int i;
    if (gid < n1_4) { s = (const float4*)w1; d = (float4*)d1; i = gid; }
    else if (gid < n1_4 + n2_4) { s = (const float4*)w2; d = (float4*)d2; i = gid - n1_4; }
    else return;
    float4 v = s[i];
    v.x = roundtf(v.x); v.y = roundtf(v.y); v.z = roundtf(v.z); v.w = roundtf(v.w);
    d[i] = v;
}

// ---- 3-phase chunked linear scan ----
__global__ void scan_phaseA_kernel() {
    int g = blockIdx.x * blockDim.x + threadIdx.x;
    if (g >= NCHK * DR) return;
    int c  = g & (DR - 1);
    int ch = g >> 10;
    size_t base = (size_t)ch * CLEN * DR + c;
    float P = 1.0f, L = 0.0f;
    for (int t = 0; t < CLEN; t++) {
        float a = g_at[base + (size_t)t * DR];
        float x = g_gx[base + (size_t)t * DR];
        L = fmaf(a, L, x);
        P *= a;
    }
    g_P[ch * DR + c] = P;
    g_L[ch * DR + c] = L;
}

__global__ void scan_phaseB_kernel() {
    int c = blockIdx.x * blockDim.x + threadIdx.x;
    if (c >= DR) return;
    float carry = 0.0f;
    for (int ch = 0; ch < NCHK; ch++) {
        g_carry[ch * DR + c] = carry;
        carry = fmaf(g_P[ch * DR + c], carry, g_L[ch * DR + c]);
    }
}

__global__ void scan_phaseC_kernel() {
    int g = blockIdx.x * blockDim.x + threadIdx.x;
    if (g >= NCHK * DR) return;
    int c  = g & (DR - 1);
    int ch = g >> 10;
    size_t base = (size_t)ch * CLEN * DR + c;
    float h = g_carry[ch * DR + c];
    for (int t = 0; t < CLEN; t++) {
        size_t o = base + (size_t)t * DR;
        h = fmaf(g_at[o], h, g_gx[o]);
        g_z[o] = roundtf(g_ab[o] * h);
    }
}

// ---------------------------------------------------------------------------
extern "C" void kernel_launch(void* const* d_in, const int* in_sizes, int n_in,
                              void* d_out, int out_size)
{
    const float* x      = (const float*)d_in[0];
    const float* w1     = (const float*)d_in[1];
    const float* b1     = (const float*)d_in[2];
    const float* conv_w = (const float*)d_in[3];
    const float* w_rg   = (const float*)d_in[4];
    const float* b_rg   = (const float*)d_in[5];
    const float* w_out  = (const float*)d_in[6];
    const float* b_out  = (const float*)d_in[7];
    const float* Lambda = (const float*)d_in[8];
    float* out = (float*)d_out;

    float *p_ab, *p_bb, *p_bcr, *p_at, *p_gx, *p_z, *p_wc, *p_zero;
    float *p_xr, *p_w1r, *p_wrgp, *p_brgp, *p_woutr, *p_lam;
    cudaGetSymbolAddress((void**)&p_ab,    g_ab);
    cudaGetSymbolAddress((void**)&p_bb,    g_bb);
    cudaGetSymbolAddress((void**)&p_bcr,   g_bcr);
    cudaGetSymbolAddress((void**)&p_at,    g_at);
    cudaGetSymbolAddress((void**)&p_gx,    g_gx);
    cudaGetSymbolAddress((void**)&p_z,     g_z);
    cudaGetSymbolAddress((void**)&p_wc,    g_wc);
    cudaGetSymbolAddress((void**)&p_zero,  g_zero);
    cudaGetSymbolAddress((void**)&p_xr,    g_xr);
    cudaGetSymbolAddress((void**)&p_w1r,   g_w1r);
    cudaGetSymbolAddress((void**)&p_wrgp,  g_wrgp);
    cudaGetSymbolAddress((void**)&p_brgp,  g_brgp);
    cudaGetSymbolAddress((void**)&p_woutr, g_woutr);
    cudaGetSymbolAddress((void**)&p_lam,   g_lam);

    const int smem_bytes = NSTAGE * STAGE_BYTES + 1024;
    cudaFuncSetAttribute(tgemm<0, 1>, cudaFuncAttributeMaxDynamicSharedMemorySize, smem_bytes);
    cudaFuncSetAttribute(tgemm<1, 5>, cudaFuncAttributeMaxDynamicSharedMemorySize, smem_bytes);
    cudaFuncSetAttribute(tgemm<0, 4>, cudaFuncAttributeMaxDynamicSharedMemorySize, smem_bytes);
    cudaFuncSetAttribute(tgemm<0, 0>, cudaFuncAttributeMaxDynamicSharedMemorySize, smem_bytes);

    // prep (4 launches so that launch #6 == conv GEMM for the ncu capture)
    prep_wrg_kernel<<<(2 * DR * DR / 4 + 255) / 256, 256>>>(w_rg, b_rg, Lambda);
    repack_conv_kernel<<<(DR * DR + 255) / 256, 256>>>(conv_w);
    round_x_kernel<<<(T_LEN * DM / 4 + 255) / 256, 256>>>(x, p_xr);
    {
        int n1_4 = 2 * DR * DM / 4, n2_4 = DM * DR / 4;
        round_w_kernel<<<(n1_4 + n2_4 + 255) / 256, 256>>>(w1, p_w1r, w_out, p_woutr, n1_4, n2_4);
    }

    // gemm1 (#5)
    {
        dim3 grid((2 * DR) / 128, T_LEN / 128);
        tgemm<0, 1><<<grid, 256, smem_bytes>>>(p_xr, p_w1r, b1, p_ab, p_bb,
                                               nullptr, nullptr, T_LEN, 2 * DR, DM);
    }
    // conv GEMM (#6 -> ncu capture target)
    {
        dim3 grid(DR / 128, T_LEN / 128);
        tgemm<1, 5><<<grid, 256, smem_bytes>>>(p_bb, p_wc, p_zero, p_bcr, nullptr,
                                               nullptr, nullptr, T_LEN, DR, DR * 4);
    }
    // gemm3 + fused gates
    {
        dim3 grid((2 * DR) / 128, T_LEN / 128);
        tgemm<0, 4><<<grid, 256, smem_bytes>>>(p_bcr, p_wrgp, p_brgp, p_at, p_gx,
                                               p_bcr, p_lam, T_LEN, 2 * DR, DR);
    }
    scan_phaseA_kernel<<<(NCHK * DR) / 256, 256>>>();
    scan_phaseB_kernel<<<(DR + 255) / 256, 256>>>();
    scan_phaseC_kernel<<<(NCHK * DR) / 256, 256>>>();
    // gemm4
    {
        dim3 grid(DM / 128, T_LEN / 128);
        tgemm<0, 0><<<grid, 256, smem_bytes>>>(p_z, p_woutr, b_out, out, nullptr,
                                               nullptr, nullptr, T_LEN, DM, DR);
    }
}